// round 1
// baseline (speedup 1.0000x reference)
#include <cuda_runtime.h>
#include <cuda_bf16.h>
#include <cstdint>

// SparseLinear: out[8192,128] = coo(ids, vals, 8192x8192) @ x[8192,128]
// Pipeline: detect id dtype -> zero counts -> row histogram -> exclusive scan
//           -> scatter into row buckets -> warp-per-row gather-reduce SpMM.

#define N_ROWS   8192
#define B_COLS   128          // 32 float4 per row
#define NNZ_CAP  4194304      // 2x headroom over reference nnz=2097152

__device__ int   g_is64;
__device__ int   g_count[N_ROWS];
__device__ int   g_start[N_ROWS + 1];
__device__ int   g_cursor[N_ROWS];
__device__ int   g_cols[NNZ_CAP];
__device__ float g_vals[NNZ_CAP];

// ---------------------------------------------------------------------------
// 0) Detect whether ids buffer is int64 (odd 32-bit words all zero) or int32.
//    Deterministic: pure function of the input bytes.
// ---------------------------------------------------------------------------
__global__ void detect_kernel(const int* __restrict__ ids32, int n_words) {
    __shared__ int s_bad;
    if (threadIdx.x == 0) s_bad = 0;
    __syncthreads();
    int bad = 0;
    for (int i = threadIdx.x; i < 2048; i += blockDim.x) {
        int p = 2 * i + 1;
        if (p < n_words && ids32[p] != 0) bad = 1;
    }
    if (bad) atomicOr(&s_bad, 1);
    __syncthreads();
    if (threadIdx.x == 0) g_is64 = s_bad ? 0 : 1;
}

// ---------------------------------------------------------------------------
// 1) Zero the row counters.
// ---------------------------------------------------------------------------
__global__ void zero_counts_kernel() {
    int i = blockIdx.x * blockDim.x + threadIdx.x;
    if (i < N_ROWS) g_count[i] = 0;
}

// ---------------------------------------------------------------------------
// 2) Row histogram. 2M RED.ADD over 8192 distinct addresses — spread enough
//    that L2 atomic serialization is not binding.
// ---------------------------------------------------------------------------
__global__ void hist_kernel(const int* __restrict__ ids32, int nnz) {
    const int is64 = g_is64;
    int stride = gridDim.x * blockDim.x;
    for (int e = blockIdx.x * blockDim.x + threadIdx.x; e < nnz; e += stride) {
        int row = is64 ? ids32[2 * e] : ids32[e];
        atomicAdd(&g_count[row], 1);
    }
}

// ---------------------------------------------------------------------------
// 3) Exclusive scan over 8192 counts (single block, 256 threads x 32 each).
//    Also seeds g_cursor and writes the sentinel g_start[8192].
// ---------------------------------------------------------------------------
__global__ void scan_kernel(int nnz) {
    __shared__ int tot[256];
    int t = threadIdx.x;
    int base = t * 32;
    int local[32];
    int s = 0;
    #pragma unroll
    for (int i = 0; i < 32; i++) { local[i] = s; s += g_count[base + i]; }
    tot[t] = s;
    __syncthreads();
    // Hillis-Steele inclusive scan over the 256 segment totals.
    for (int off = 1; off < 256; off <<= 1) {
        int v = (t >= off) ? tot[t - off] : 0;
        __syncthreads();
        tot[t] += v;
        __syncthreads();
    }
    int segbase = (t == 0) ? 0 : tot[t - 1];
    #pragma unroll
    for (int i = 0; i < 32; i++) {
        int v = segbase + local[i];
        g_start[base + i]  = v;
        g_cursor[base + i] = v;
    }
    if (t == 255) g_start[N_ROWS] = tot[255];
}

// ---------------------------------------------------------------------------
// 4) Scatter (col, val) into the per-row buckets.
// ---------------------------------------------------------------------------
__global__ void scatter_kernel(const int* __restrict__ ids32,
                               const float* __restrict__ vals, int nnz) {
    const int is64 = g_is64;
    int stride = gridDim.x * blockDim.x;
    for (int e = blockIdx.x * blockDim.x + threadIdx.x; e < nnz; e += stride) {
        int row, col;
        if (is64) {
            row = ids32[2 * e];
            col = ids32[2 * (nnz + e)];
        } else {
            row = ids32[e];
            col = ids32[nnz + e];
        }
        int p = atomicAdd(&g_cursor[row], 1);
        if (p < NNZ_CAP) {
            g_cols[p] = col;
            g_vals[p] = vals[e];
        }
    }
}

// ---------------------------------------------------------------------------
// 5) SpMM: one warp per output row. Lane l owns float4 columns [4l, 4l+4).
//    (col, val) are loaded coalesced 32-at-a-time and broadcast via shfl;
//    each nnz issues one LDG.128 gather of x's row (512 B/warp, ~all L2 hits).
// ---------------------------------------------------------------------------
__global__ void spmm_kernel(const float* __restrict__ x,
                            float* __restrict__ out) {
    int gwarp = (blockIdx.x * blockDim.x + threadIdx.x) >> 5;
    int lane  = threadIdx.x & 31;
    if (gwarp >= N_ROWS) return;

    int s = g_start[gwarp];
    int e = g_start[gwarp + 1];

    const float4* __restrict__ x4 = reinterpret_cast<const float4*>(x);
    float4 acc = make_float4(0.f, 0.f, 0.f, 0.f);

    for (int base = s; base < e; base += 32) {
        int idx = base + lane;
        int   c = 0;
        float v = 0.f;
        if (idx < e) { c = g_cols[idx]; v = g_vals[idx]; }
        int cnt = e - base; if (cnt > 32) cnt = 32;
        #pragma unroll 4
        for (int j = 0; j < cnt; j++) {
            int   cj = __shfl_sync(0xffffffffu, c, j);
            float vj = __shfl_sync(0xffffffffu, v, j);
            float4 xr = __ldg(&x4[cj * 32 + lane]);
            acc.x += vj * xr.x;
            acc.y += vj * xr.y;
            acc.z += vj * xr.z;
            acc.w += vj * xr.w;
        }
    }
    reinterpret_cast<float4*>(out)[gwarp * 32 + lane] = acc;
}

// ---------------------------------------------------------------------------
// Launch
// ---------------------------------------------------------------------------
extern "C" void kernel_launch(void* const* d_in, const int* in_sizes, int n_in,
                              void* d_out, int out_size) {
    const int*   ids32 = (const int*)d_in[0];    // int64 or int32 (detected)
    const float* vals  = (const float*)d_in[1];  // [nnz]
    const float* x     = (const float*)d_in[2];  // [8192, 128]
    float*       out   = (float*)d_out;          // [8192, 128]

    int nnz = in_sizes[1];
    // If ids is int64, in_sizes[0] counts int64 elements (= 2*nnz); the raw
    // word count differs, but the detector works off the first 4096 words
    // which exist in both layouts (nnz >> 2048).
    int n_words = in_sizes[0] * 2;  // conservative upper bound for int64 case

    detect_kernel<<<1, 256>>>(ids32, n_words);
    zero_counts_kernel<<<(N_ROWS + 255) / 256, 256>>>();

    int blocks = 1184;  // 148 SMs * 8
    hist_kernel<<<blocks, 256>>>(ids32, nnz);
    scan_kernel<<<1, 256>>>(nnz);
    scatter_kernel<<<blocks, 256>>>(ids32, vals, nnz);

    // 8192 rows, 1 warp each, 4 warps per 128-thread block.
    spmm_kernel<<<N_ROWS / 4, 128>>>(x, out);
}

// round 2
// speedup vs baseline: 1.6559x; 1.6559x over previous
#include <cuda_runtime.h>
#include <cuda_fp16.h>
#include <cstdint>

// SparseLinear: out[8192,128] = coo(ids, vals, 8192x8192) @ x[8192,128]
// v2: fixed-capacity row buckets (no hist/scan), packed (col,val), fp16 x.
// Launches: init (detect + zero + x->fp16) -> scatter -> spmm -> overflow fixup.

#define N_ROWS    8192
#define ROW_CAP   512          // mean nnz/row = 256; Poisson tail makes 512 safe
#define OVER_CAP  65536

__device__ int     g_is64;
__device__ int     g_count[N_ROWS];
__device__ int     g_over_cnt;
__device__ uint4   g_over[OVER_CAP];            // (row, col, val_bits, 0)
__device__ uint2   g_pack[N_ROWS * ROW_CAP];    // (col, val_bits)  32 MB
__device__ __half2 g_xh[N_ROWS * 64];           // x in fp16, 2 MB (L2-resident)

// ---------------------------------------------------------------------------
// 1) init: detect id dtype (block 0), zero counters, convert x -> fp16.
// ---------------------------------------------------------------------------
__global__ void init_kernel(const int* __restrict__ ids32,
                            const float* __restrict__ x) {
    int tid    = blockIdx.x * blockDim.x + threadIdx.x;
    int stride = gridDim.x * blockDim.x;

    // zero row counters + overflow counter
    for (int i = tid; i < N_ROWS; i += stride) g_count[i] = 0;
    if (tid == 0) g_over_cnt = 0;

    // dtype detect: int64 ids of values < 8192 have all-zero odd 32-bit words.
    if (blockIdx.x == 0) {
        __shared__ int s_bad;
        if (threadIdx.x == 0) s_bad = 0;
        __syncthreads();
        int bad = 0;
        for (int i = threadIdx.x; i < 2048; i += blockDim.x)
            if (ids32[2 * i + 1] != 0) bad = 1;
        if (bad) atomicOr(&s_bad, 1);
        __syncthreads();
        if (threadIdx.x == 0) g_is64 = s_bad ? 0 : 1;
    }

    // convert x (1M floats) to fp16: float4 -> 2x half2
    const float4* __restrict__ x4 = reinterpret_cast<const float4*>(x);
    for (int i = tid; i < N_ROWS * 32; i += stride) {
        float4 v = x4[i];
        g_xh[2 * i]     = __floats2half2_rn(v.x, v.y);
        g_xh[2 * i + 1] = __floats2half2_rn(v.z, v.w);
    }
}

// ---------------------------------------------------------------------------
// 2) scatter: single pass, atomic cursor per row, packed 8-byte payload.
// ---------------------------------------------------------------------------
__global__ void scatter_kernel(const int* __restrict__ ids32,
                               const float* __restrict__ vals, int nnz) {
    const int is64 = g_is64;
    int stride = gridDim.x * blockDim.x;
    for (int e = blockIdx.x * blockDim.x + threadIdx.x; e < nnz; e += stride) {
        int row, col;
        if (is64) {
            row = ids32[2 * e];
            col = ids32[2 * (nnz + e)];
        } else {
            row = ids32[e];
            col = ids32[nnz + e];
        }
        float v = vals[e];
        int p = atomicAdd(&g_count[row], 1);
        if (p < ROW_CAP) {
            g_pack[row * ROW_CAP + p] = make_uint2((unsigned)col,
                                                   __float_as_uint(v));
        } else {
            int q = atomicAdd(&g_over_cnt, 1);
            if (q < OVER_CAP)
                g_over[q] = make_uint4((unsigned)row, (unsigned)col,
                                       __float_as_uint(v), 0u);
        }
    }
}

// ---------------------------------------------------------------------------
// 3) spmm: one warp per row. Lane l owns cols [4l, 4l+4) (one uint2 of half2).
//    Packed (col,val) loaded coalesced, broadcast via shfl; per-nnz gather is
//    a 256B/warp LDG.64 of the fp16 x row — all L2 hits.
// ---------------------------------------------------------------------------
__global__ void spmm_kernel(float* __restrict__ out) {
    int gwarp = (blockIdx.x * blockDim.x + threadIdx.x) >> 5;
    int lane  = threadIdx.x & 31;
    if (gwarp >= N_ROWS) return;

    int cnt = g_count[gwarp];
    if (cnt > ROW_CAP) cnt = ROW_CAP;
    const uint2* __restrict__ pk = g_pack + gwarp * ROW_CAP;
    const uint2* __restrict__ xh = reinterpret_cast<const uint2*>(g_xh);

    float a0 = 0.f, a1 = 0.f, a2 = 0.f, a3 = 0.f;

    for (int base = 0; base < cnt; base += 32) {
        int idx = base + lane;
        uint2 e = make_uint2(0u, 0u);
        if (idx < cnt) e = pk[idx];
        int m = cnt - base; if (m > 32) m = 32;
        #pragma unroll 4
        for (int j = 0; j < m; j++) {
            unsigned cj = __shfl_sync(0xffffffffu, e.x, j);
            float    vj = __uint_as_float(__shfl_sync(0xffffffffu, e.y, j));
            uint2 xr = __ldg(&xh[cj * 32 + lane]);
            float2 f0 = __half22float2(*reinterpret_cast<__half2*>(&xr.x));
            float2 f1 = __half22float2(*reinterpret_cast<__half2*>(&xr.y));
            a0 += vj * f0.x;
            a1 += vj * f0.y;
            a2 += vj * f1.x;
            a3 += vj * f1.y;
        }
    }
    reinterpret_cast<float4*>(out)[gwarp * 32 + lane] =
        make_float4(a0, a1, a2, a3);
}

// ---------------------------------------------------------------------------
// 4) overflow fixup: normally zero entries; atomicAdd leftovers onto out
//    using the original fp32 x.
// ---------------------------------------------------------------------------
__global__ void fixup_kernel(const float* __restrict__ x,
                             float* __restrict__ out) {
    int n = g_over_cnt;
    if (n > OVER_CAP) n = OVER_CAP;
    int gwarp  = (blockIdx.x * blockDim.x + threadIdx.x) >> 5;
    int lane   = threadIdx.x & 31;
    int nwarps = (gridDim.x * blockDim.x) >> 5;
    for (int q = gwarp; q < n; q += nwarps) {
        uint4 e = g_over[q];
        int   row = (int)e.x, col = (int)e.y;
        float v   = __uint_as_float(e.z);
        #pragma unroll
        for (int k = 0; k < 4; k++) {
            int c = 4 * lane + k;
            atomicAdd(&out[row * 128 + c], v * x[col * 128 + c]);
        }
    }
}

// ---------------------------------------------------------------------------
// Launch
// ---------------------------------------------------------------------------
extern "C" void kernel_launch(void* const* d_in, const int* in_sizes, int n_in,
                              void* d_out, int out_size) {
    const int*   ids32 = (const int*)d_in[0];    // int64 or int32 (detected)
    const float* vals  = (const float*)d_in[1];  // [nnz]
    const float* x     = (const float*)d_in[2];  // [8192, 128] fp32
    float*       out   = (float*)d_out;          // [8192, 128] fp32

    int nnz = in_sizes[1];

    init_kernel<<<592, 256>>>(ids32, x);              // 148 SMs * 4
    scatter_kernel<<<1184, 256>>>(ids32, vals, nnz);  // 148 SMs * 8
    spmm_kernel<<<N_ROWS / 8, 256>>>(out);            // 1 warp / row
    fixup_kernel<<<64, 256>>>(x, out);
}